// round 5
// baseline (speedup 1.0000x reference)
#include <cuda_runtime.h>
#include <cuda_bf16.h>
#include <math.h>

// Problem constants
#define L_SEQ   2048
#define BATCH   2
#define D_MODEL 1024
#define NHEAD   16
#define D_K     64
#define D_ROPE  32
#define M_ROWS  (L_SEQ * BATCH)        // 4096
#define N_COLS  (3 * D_MODEL)          // 3072
#define K_DIM   D_MODEL                // 1024

// Scratch (device globals — no runtime allocation allowed)
__device__ float g_qkv[M_ROWS * N_COLS];                 // [r][e]   ~50 MB
__device__ float g_Q[NHEAD * BATCH * L_SEQ * D_K];       // [(h*2+b)][l][d]
__device__ float g_K[NHEAD * BATCH * L_SEQ * D_K];
__device__ float g_V[NHEAD * BATCH * L_SEQ * D_K];

// ---------------------------------------------------------------------------
// Kernel 1: QKV projection  C[r][e] = sum_d X[r][d] * W[e][d]
// 128x128 tile, BK=16, 256 threads, 8x8 microtile
// ---------------------------------------------------------------------------
__global__ __launch_bounds__(256) void qkv_gemm(const float* __restrict__ X,
                                                const float* __restrict__ W,
                                                float* __restrict__ C) {
    __shared__ float As[16][128];
    __shared__ float Bs[16][128];

    const int tid = threadIdx.x;
    const int bx = blockIdx.x;   // N tile: 0..23
    const int by = blockIdx.y;   // M tile: 0..31

    const int lrow = tid >> 2;          // 0..63
    const int lcol = (tid & 3) << 2;    // 0,4,8,12

    const int tx = tid & 15;            // 0..15 -> N
    const int ty = tid >> 4;            // 0..15 -> M

    const float* Aptr = X + (size_t)(by * 128) * K_DIM;
    const float* Bptr = W + (size_t)(bx * 128) * K_DIM;

    float acc[8][8];
#pragma unroll
    for (int i = 0; i < 8; i++)
#pragma unroll
        for (int j = 0; j < 8; j++) acc[i][j] = 0.f;

    for (int k0 = 0; k0 < K_DIM; k0 += 16) {
#pragma unroll
        for (int r = 0; r < 128; r += 64) {
            float4 a4 = *(const float4*)(Aptr + (size_t)(lrow + r) * K_DIM + k0 + lcol);
            As[lcol + 0][lrow + r] = a4.x;
            As[lcol + 1][lrow + r] = a4.y;
            As[lcol + 2][lrow + r] = a4.z;
            As[lcol + 3][lrow + r] = a4.w;
            float4 b4 = *(const float4*)(Bptr + (size_t)(lrow + r) * K_DIM + k0 + lcol);
            Bs[lcol + 0][lrow + r] = b4.x;
            Bs[lcol + 1][lrow + r] = b4.y;
            Bs[lcol + 2][lrow + r] = b4.z;
            Bs[lcol + 3][lrow + r] = b4.w;
        }
        __syncthreads();

#pragma unroll
        for (int k = 0; k < 16; k++) {
            float a[8], b[8];
            *(float4*)(a + 0) = *(const float4*)(&As[k][ty * 8 + 0]);
            *(float4*)(a + 4) = *(const float4*)(&As[k][ty * 8 + 4]);
            *(float4*)(b + 0) = *(const float4*)(&Bs[k][tx * 8 + 0]);
            *(float4*)(b + 4) = *(const float4*)(&Bs[k][tx * 8 + 4]);
#pragma unroll
            for (int i = 0; i < 8; i++)
#pragma unroll
                for (int j = 0; j < 8; j++)
                    acc[i][j] = fmaf(a[i], b[j], acc[i][j]);
        }
        __syncthreads();
    }

#pragma unroll
    for (int i = 0; i < 8; i++) {
        size_t row = (size_t)(by * 128 + ty * 8 + i);
        float* cp = C + row * N_COLS + bx * 128 + tx * 8;
        *(float4*)(cp + 0) = *(const float4*)(&acc[i][0]);
        *(float4*)(cp + 4) = *(const float4*)(&acc[i][4]);
    }
}

// ---------------------------------------------------------------------------
// Kernel 2: RoPE + scatter qkv -> Q (scaled), K, V in [(h*B+b)][l][d] layout
// ---------------------------------------------------------------------------
__global__ __launch_bounds__(256) void rope_scatter(const float* __restrict__ qkv,
                                                    float* __restrict__ Qo,
                                                    float* __restrict__ Ko,
                                                    float* __restrict__ Vo) {
    int idx = blockIdx.x * blockDim.x + threadIdx.x;   // over L*B*H*64 = 4.19M
    if (idx >= L_SEQ * BATCH * NHEAD * D_K) return;
    const int d = idx & 63;
    const int h = (idx >> 6) & 15;
    const int r = idx >> 10;          // 0..4095  (= l*B + b)
    const int l = r >> 1;
    const int b = r & 1;

    const float* row = qkv + (size_t)r * N_COLS + h * (3 * D_K);
    float q = row[d];
    float k = row[D_K + d];
    float v = row[2 * D_K + d];

    if (d < D_ROPE) {
        const int i = d & 15;   // freq index
        // theta_i = 10000^(-i/16) = 2^(-i * log2(10000)/16), double -> f32
        float theta = (float)exp2(-(double)i * (13.287712379549449 / 16.0));
        float ang = (float)l * theta;
        float cs = cosf(ang);
        float sn = sinf(ang);
        if (d < 16) {
            q = q * cs - row[d + 16] * sn;
            k = k * cs - row[D_K + d + 16] * sn;
        } else {
            q = q * cs + row[d - 16] * sn;
            k = k * cs + row[D_K + d - 16] * sn;
        }
    }
    size_t o = ((size_t)(h * BATCH + b) * L_SEQ + l) * D_K + d;
    Qo[o] = q * 0.125f;     // fold in 1/sqrt(64)
    Ko[o] = k;
    Vo[o] = v;
}

// ---------------------------------------------------------------------------
// Kernel 3: Flash attention fp32.  One (h,b) pair per blockIdx.y,
// BQ=128 queries per block (1 query per thread), BK=16 key tile in smem.
// ---------------------------------------------------------------------------
#define AQ 128
#define AK 16
#define QSTRIDE 68   // floats; padded so float4 LDS is conflict-free

__global__ __launch_bounds__(128) void flash_attn(const float* __restrict__ Q,
                                                  const float* __restrict__ K,
                                                  const float* __restrict__ V,
                                                  float* __restrict__ out) {
    __shared__ float Qs[AQ * QSTRIDE];     // 34816 B
    __shared__ float Ks[AK * D_K];         // 4096 B
    __shared__ float Vs[AK * D_K];         // 4096 B

    const int tid = threadIdx.x;
    const int hb = blockIdx.y;             // h*BATCH + b
    const int q0 = blockIdx.x * AQ;

    const float* Qg = Q + ((size_t)hb * L_SEQ + q0) * D_K;
    const float* Kg = K + (size_t)hb * L_SEQ * D_K;
    const float* Vg = V + (size_t)hb * L_SEQ * D_K;

    // Load Q tile: 128 rows x 16 float4
    for (int i = tid; i < AQ * 16; i += 128) {
        int row = i >> 4, c4 = i & 15;
        float4 v = *(const float4*)(Qg + (size_t)row * D_K + c4 * 4);
        *(float4*)(Qs + row * QSTRIDE + c4 * 4) = v;
    }

    float O[D_K];
#pragma unroll
    for (int d = 0; d < D_K; d++) O[d] = 0.f;
    float m = -1e30f, lsum = 0.f;

    for (int t = 0; t < L_SEQ / AK; t++) {
        __syncthreads();
        // Load K/V tile: 16 rows x 16 float4 each; 2 per thread per array
        for (int i = tid; i < AK * 16; i += 128) {
            int row = i >> 4, c4 = i & 15;
            size_t g = (size_t)(t * AK + row) * D_K + c4 * 4;
            *(float4*)(Ks + row * D_K + c4 * 4) = *(const float4*)(Kg + g);
            *(float4*)(Vs + row * D_K + c4 * 4) = *(const float4*)(Vg + g);
        }
        __syncthreads();

        // Scores: s[k] = dot(Q[tid], K[k])
        float s[AK];
#pragma unroll
        for (int k = 0; k < AK; k++) s[k] = 0.f;
#pragma unroll
        for (int d4 = 0; d4 < 16; d4++) {
            float4 q4 = *(const float4*)(Qs + tid * QSTRIDE + d4 * 4);
#pragma unroll
            for (int k = 0; k < AK; k++) {
                float4 kv = *(const float4*)(Ks + k * D_K + d4 * 4);
                s[k] = fmaf(q4.x, kv.x, s[k]);
                s[k] = fmaf(q4.y, kv.y, s[k]);
                s[k] = fmaf(q4.z, kv.z, s[k]);
                s[k] = fmaf(q4.w, kv.w, s[k]);
            }
        }

        // Online softmax
        float mx = m;
#pragma unroll
        for (int k = 0; k < AK; k++) mx = fmaxf(mx, s[k]);
        float corr = __expf(m - mx);
        float psum = 0.f;
#pragma unroll
        for (int k = 0; k < AK; k++) {
            s[k] = __expf(s[k] - mx);
            psum += s[k];
        }
        m = mx;
        lsum = lsum * corr + psum;
#pragma unroll
        for (int d = 0; d < D_K; d++) O[d] *= corr;

        // O += P @ V
#pragma unroll
        for (int d4 = 0; d4 < 16; d4++) {
#pragma unroll
            for (int k = 0; k < AK; k++) {
                float4 vv = *(const float4*)(Vs + k * D_K + d4 * 4);
                O[d4 * 4 + 0] = fmaf(s[k], vv.x, O[d4 * 4 + 0]);
                O[d4 * 4 + 1] = fmaf(s[k], vv.y, O[d4 * 4 + 1]);
                O[d4 * 4 + 2] = fmaf(s[k], vv.z, O[d4 * 4 + 2]);
                O[d4 * 4 + 3] = fmaf(s[k], vv.w, O[d4 * 4 + 3]);
            }
        }
    }

    const float inv = 1.f / lsum;
    const int h = hb >> 1, b = hb & 1;
    const int ql = q0 + tid;                       // global query position l
    float* op = out + ((size_t)ql * BATCH + b) * D_MODEL + h * D_K;
#pragma unroll
    for (int d4 = 0; d4 < 16; d4++) {
        float4 v;
        v.x = O[d4 * 4 + 0] * inv;
        v.y = O[d4 * 4 + 1] * inv;
        v.z = O[d4 * 4 + 2] * inv;
        v.w = O[d4 * 4 + 3] * inv;
        *(float4*)(op + d4 * 4) = v;
    }
}

// ---------------------------------------------------------------------------
extern "C" void kernel_launch(void* const* d_in, const int* in_sizes, int n_in,
                              void* d_out, int out_size) {
    const float* x = (const float*)d_in[0];          // [L, B, 1024]
    const float* w = (const float*)d_in[1];          // [3072, 1024]
    float* out = (float*)d_out;                      // [L, B, 1024]

    float *qkv, *Qp, *Kp, *Vp;
    cudaGetSymbolAddress((void**)&qkv, g_qkv);
    cudaGetSymbolAddress((void**)&Qp, g_Q);
    cudaGetSymbolAddress((void**)&Kp, g_K);
    cudaGetSymbolAddress((void**)&Vp, g_V);

    dim3 ggrid(N_COLS / 128, M_ROWS / 128);
    qkv_gemm<<<ggrid, 256>>>(x, w, qkv);

    int total = L_SEQ * BATCH * NHEAD * D_K;
    rope_scatter<<<(total + 255) / 256, 256>>>(qkv, Qp, Kp, Vp);

    dim3 agrid(L_SEQ / AQ, NHEAD * BATCH);
    flash_attn<<<agrid, 128>>>(Qp, Kp, Vp, out);
}

// round 10
// speedup vs baseline: 1.1608x; 1.1608x over previous
#include <cuda_runtime.h>
#include <cuda_bf16.h>
#include <math.h>
#include <stdint.h>

// Problem constants
#define L_SEQ   2048
#define BATCH   2
#define D_MODEL 1024
#define NHEAD   16
#define D_K     64
#define D_ROPE  32
#define M_ROWS  (L_SEQ * BATCH)        // 4096
#define N_COLS  (3 * D_MODEL)          // 3072
#define K_DIM   D_MODEL                // 1024

// Scratch (device globals — no runtime allocation allowed)
__device__ float g_qkv[M_ROWS * N_COLS];                 // [r][e]
__device__ float g_Q[NHEAD * BATCH * L_SEQ * D_K];       // [(h*2+b)][l][d]
__device__ float g_K[NHEAD * BATCH * L_SEQ * D_K];
__device__ float g_V[NHEAD * BATCH * L_SEQ * D_K];

// Split-bf16 copies of X and W (hi + residual lo)
__device__ __nv_bfloat16 g_Xhi[M_ROWS * K_DIM];
__device__ __nv_bfloat16 g_Xlo[M_ROWS * K_DIM];
__device__ __nv_bfloat16 g_Whi[N_COLS * K_DIM];
__device__ __nv_bfloat16 g_Wlo[N_COLS * K_DIM];

// ---------------------------------------------------------------------------
// Kernel 0: fp32 -> split bf16 (hi = rn(x), lo = rn(x - hi))
// Processes 4 floats per thread.
// ---------------------------------------------------------------------------
__global__ __launch_bounds__(256) void split_bf16(const float* __restrict__ src,
                                                  __nv_bfloat16* __restrict__ hi,
                                                  __nv_bfloat16* __restrict__ lo,
                                                  int n4) {
    int i = blockIdx.x * blockDim.x + threadIdx.x;
    if (i >= n4) return;
    float4 v = ((const float4*)src)[i];
    __nv_bfloat16 h0 = __float2bfloat16_rn(v.x);
    __nv_bfloat16 h1 = __float2bfloat16_rn(v.y);
    __nv_bfloat16 h2 = __float2bfloat16_rn(v.z);
    __nv_bfloat16 h3 = __float2bfloat16_rn(v.w);
    __nv_bfloat16 l0 = __float2bfloat16_rn(v.x - __bfloat162float(h0));
    __nv_bfloat16 l1 = __float2bfloat16_rn(v.y - __bfloat162float(h1));
    __nv_bfloat16 l2 = __float2bfloat16_rn(v.z - __bfloat162float(h2));
    __nv_bfloat16 l3 = __float2bfloat16_rn(v.w - __bfloat162float(h3));
    uint2 hv, lv;
    hv.x = (uint32_t)__bfloat16_as_ushort(h0) | ((uint32_t)__bfloat16_as_ushort(h1) << 16);
    hv.y = (uint32_t)__bfloat16_as_ushort(h2) | ((uint32_t)__bfloat16_as_ushort(h3) << 16);
    lv.x = (uint32_t)__bfloat16_as_ushort(l0) | ((uint32_t)__bfloat16_as_ushort(l1) << 16);
    lv.y = (uint32_t)__bfloat16_as_ushort(l2) | ((uint32_t)__bfloat16_as_ushort(l3) << 16);
    ((uint2*)hi)[i] = hv;
    ((uint2*)lo)[i] = lv;
}

// ---------------------------------------------------------------------------
// mma.sync m16n8k16 bf16 (baseline PTX — works on plain sm_103 target)
// ---------------------------------------------------------------------------
__device__ __forceinline__ void mma16816(float* c,
                                         uint32_t a0, uint32_t a1, uint32_t a2, uint32_t a3,
                                         uint32_t b0, uint32_t b1) {
    asm volatile(
        "mma.sync.aligned.m16n8k16.row.col.f32.bf16.bf16.f32 "
        "{%0,%1,%2,%3}, {%4,%5,%6,%7}, {%8,%9}, {%0,%1,%2,%3};"
        : "+f"(c[0]), "+f"(c[1]), "+f"(c[2]), "+f"(c[3])
        : "r"(a0), "r"(a1), "r"(a2), "r"(a3), "r"(b0), "r"(b1));
}

// ---------------------------------------------------------------------------
// Kernel 1: QKV projection C[r][e] = sum_d X[r][d] * W[e][d]
// Tensor-core bf16 split (3 terms), BM=128, BN=128, BK=32.
// 8 warps: warp_m = wid&1 (64 rows), warp_n = wid>>1 (32 cols).
// smem bf16 tiles padded to row stride 40 (conflict-free frag LDS).
// ---------------------------------------------------------------------------
#define GBK 32
#define APAD 40

__global__ __launch_bounds__(256) void qkv_gemm_mma(const __nv_bfloat16* __restrict__ Xhi,
                                                    const __nv_bfloat16* __restrict__ Xlo,
                                                    const __nv_bfloat16* __restrict__ Whi,
                                                    const __nv_bfloat16* __restrict__ Wlo,
                                                    float* __restrict__ C) {
    __shared__ __align__(16) __nv_bfloat16 Ahi[128 * APAD];
    __shared__ __align__(16) __nv_bfloat16 Alo[128 * APAD];
    __shared__ __align__(16) __nv_bfloat16 Bhi[128 * APAD];
    __shared__ __align__(16) __nv_bfloat16 Blo[128 * APAD];

    const int tid = threadIdx.x;
    const int lane = tid & 31;
    const int wid = tid >> 5;
    const int warp_m = wid & 1;        // 0..1 -> 64 rows each
    const int warp_n = wid >> 1;       // 0..3 -> 32 cols each
    const int qr = lane >> 2;          // 0..7
    const int qc = lane & 3;           // 0..3

    const int bm = blockIdx.y * 128;
    const int bn = blockIdx.x * 128;

    float acc[4][4][4];
#pragma unroll
    for (int fm = 0; fm < 4; fm++)
#pragma unroll
        for (int fn = 0; fn < 4; fn++)
#pragma unroll
            for (int x = 0; x < 4; x++) acc[fm][fn][x] = 0.f;

    for (int ch = 0; ch < K_DIM / GBK; ch++) {
        const int k0 = ch * GBK;
        // Load A/B tiles: 128 rows x 32 bf16 per buffer; uint4 = 8 bf16, 4/row.
#pragma unroll
        for (int it = 0; it < 2; it++) {
            const int s = it * 256 + tid;       // 0..511
            const int row = s >> 2;
            const int c8 = s & 3;
            const size_t goff = (size_t)row * K_DIM + k0 + c8 * 8;
            const int soff = row * APAD + c8 * 8;
            *(uint4*)(Ahi + soff) = *(const uint4*)(Xhi + (size_t)bm * K_DIM + goff);
            *(uint4*)(Alo + soff) = *(const uint4*)(Xlo + (size_t)bm * K_DIM + goff);
            *(uint4*)(Bhi + soff) = *(const uint4*)(Whi + (size_t)bn * K_DIM + goff);
            *(uint4*)(Blo + soff) = *(const uint4*)(Wlo + (size_t)bn * K_DIM + goff);
        }
        __syncthreads();

        const __nv_bfloat16* Ap[3] = {Ahi, Ahi, Alo};
        const __nv_bfloat16* Bp[3] = {Bhi, Blo, Bhi};
#pragma unroll
        for (int t = 0; t < 3; t++) {
            const __nv_bfloat16* As = Ap[t];
            const __nv_bfloat16* Bs = Bp[t];
#pragma unroll
            for (int ks = 0; ks < 2; ks++) {
                const int koff = ks * 16 + qc * 2;
                uint32_t a[4][4];
#pragma unroll
                for (int fm = 0; fm < 4; fm++) {
                    const int r0 = warp_m * 64 + fm * 16 + qr;
                    a[fm][0] = *(const uint32_t*)(As + r0 * APAD + koff);
                    a[fm][1] = *(const uint32_t*)(As + (r0 + 8) * APAD + koff);
                    a[fm][2] = *(const uint32_t*)(As + r0 * APAD + koff + 8);
                    a[fm][3] = *(const uint32_t*)(As + (r0 + 8) * APAD + koff + 8);
                }
                uint32_t b[4][2];
#pragma unroll
                for (int fn = 0; fn < 4; fn++) {
                    const int n0 = warp_n * 32 + fn * 8 + qr;
                    b[fn][0] = *(const uint32_t*)(Bs + n0 * APAD + koff);
                    b[fn][1] = *(const uint32_t*)(Bs + n0 * APAD + koff + 8);
                }
#pragma unroll
                for (int fm = 0; fm < 4; fm++)
#pragma unroll
                    for (int fn = 0; fn < 4; fn++)
                        mma16816(acc[fm][fn], a[fm][0], a[fm][1], a[fm][2], a[fm][3],
                                 b[fn][0], b[fn][1]);
            }
        }
        __syncthreads();
    }

    // Epilogue: fp32 stores (float2 per fragment row)
#pragma unroll
    for (int fm = 0; fm < 4; fm++) {
        const int r0 = bm + warp_m * 64 + fm * 16 + qr;
#pragma unroll
        for (int fn = 0; fn < 4; fn++) {
            const int col = bn + warp_n * 32 + fn * 8 + qc * 2;
            float2 v0 = {acc[fm][fn][0], acc[fm][fn][1]};
            float2 v1 = {acc[fm][fn][2], acc[fm][fn][3]};
            *(float2*)(C + (size_t)r0 * N_COLS + col) = v0;
            *(float2*)(C + (size_t)(r0 + 8) * N_COLS + col) = v1;
        }
    }
}

// ---------------------------------------------------------------------------
// Kernel 2: RoPE + scatter qkv -> Q (scaled), K, V in [(h*B+b)][l][d] layout
// ---------------------------------------------------------------------------
__global__ __launch_bounds__(256) void rope_scatter(const float* __restrict__ qkv,
                                                    float* __restrict__ Qo,
                                                    float* __restrict__ Ko,
                                                    float* __restrict__ Vo) {
    int idx = blockIdx.x * blockDim.x + threadIdx.x;
    if (idx >= L_SEQ * BATCH * NHEAD * D_K) return;
    const int d = idx & 63;
    const int h = (idx >> 6) & 15;
    const int r = idx >> 10;
    const int l = r >> 1;
    const int b = r & 1;

    const float* row = qkv + (size_t)r * N_COLS + h * (3 * D_K);
    float q = row[d];
    float k = row[D_K + d];
    float v = row[2 * D_K + d];

    if (d < D_ROPE) {
        const int i = d & 15;
        float theta = (float)exp2(-(double)i * (13.287712379549449 / 16.0));
        float ang = (float)l * theta;
        float cs = cosf(ang);
        float sn = sinf(ang);
        if (d < 16) {
            q = q * cs - row[d + 16] * sn;
            k = k * cs - row[D_K + d + 16] * sn;
        } else {
            q = q * cs + row[d - 16] * sn;
            k = k * cs + row[D_K + d - 16] * sn;
        }
    }
    size_t o = ((size_t)(h * BATCH + b) * L_SEQ + l) * D_K + d;
    Qo[o] = q * 0.125f;
    Ko[o] = k;
    Vo[o] = v;
}

// ---------------------------------------------------------------------------
// Kernel 3: Flash attention fp32 (unchanged — next round's tensorization target)
// ---------------------------------------------------------------------------
#define AQ 128
#define AK 16
#define QSTRIDE 68

__global__ __launch_bounds__(128) void flash_attn(const float* __restrict__ Q,
                                                  const float* __restrict__ K,
                                                  const float* __restrict__ V,
                                                  float* __restrict__ out) {
    __shared__ float Qs[AQ * QSTRIDE];
    __shared__ float Ks[AK * D_K];
    __shared__ float Vs[AK * D_K];

    const int tid = threadIdx.x;
    const int hb = blockIdx.y;
    const int q0 = blockIdx.x * AQ;

    const float* Qg = Q + ((size_t)hb * L_SEQ + q0) * D_K;
    const float* Kg = K + (size_t)hb * L_SEQ * D_K;
    const float* Vg = V + (size_t)hb * L_SEQ * D_K;

    for (int i = tid; i < AQ * 16; i += 128) {
        int row = i >> 4, c4 = i & 15;
        float4 v = *(const float4*)(Qg + (size_t)row * D_K + c4 * 4);
        *(float4*)(Qs + row * QSTRIDE + c4 * 4) = v;
    }

    float O[D_K];
#pragma unroll
    for (int d = 0; d < D_K; d++) O[d] = 0.f;
    float m = -1e30f, lsum = 0.f;

    for (int t = 0; t < L_SEQ / AK; t++) {
        __syncthreads();
        for (int i = tid; i < AK * 16; i += 128) {
            int row = i >> 4, c4 = i & 15;
            size_t g = (size_t)(t * AK + row) * D_K + c4 * 4;
            *(float4*)(Ks + row * D_K + c4 * 4) = *(const float4*)(Kg + g);
            *(float4*)(Vs + row * D_K + c4 * 4) = *(const float4*)(Vg + g);
        }
        __syncthreads();

        float s[AK];
#pragma unroll
        for (int k = 0; k < AK; k++) s[k] = 0.f;
#pragma unroll
        for (int d4 = 0; d4 < 16; d4++) {
            float4 q4 = *(const float4*)(Qs + tid * QSTRIDE + d4 * 4);
#pragma unroll
            for (int k = 0; k < AK; k++) {
                float4 kv = *(const float4*)(Ks + k * D_K + d4 * 4);
                s[k] = fmaf(q4.x, kv.x, s[k]);
                s[k] = fmaf(q4.y, kv.y, s[k]);
                s[k] = fmaf(q4.z, kv.z, s[k]);
                s[k] = fmaf(q4.w, kv.w, s[k]);
            }
        }

        float mx = m;
#pragma unroll
        for (int k = 0; k < AK; k++) mx = fmaxf(mx, s[k]);
        float corr = __expf(m - mx);
        float psum = 0.f;
#pragma unroll
        for (int k = 0; k < AK; k++) {
            s[k] = __expf(s[k] - mx);
            psum += s[k];
        }
        m = mx;
        lsum = lsum * corr + psum;
#pragma unroll
        for (int d = 0; d < D_K; d++) O[d] *= corr;

#pragma unroll
        for (int d4 = 0; d4 < 16; d4++) {
#pragma unroll
            for (int k = 0; k < AK; k++) {
                float4 vv = *(const float4*)(Vs + k * D_K + d4 * 4);
                O[d4 * 4 + 0] = fmaf(s[k], vv.x, O[d4 * 4 + 0]);
                O[d4 * 4 + 1] = fmaf(s[k], vv.y, O[d4 * 4 + 1]);
                O[d4 * 4 + 2] = fmaf(s[k], vv.z, O[d4 * 4 + 2]);
                O[d4 * 4 + 3] = fmaf(s[k], vv.w, O[d4 * 4 + 3]);
            }
        }
    }

    const float inv = 1.f / lsum;
    const int h = hb >> 1, b = hb & 1;
    const int ql = q0 + tid;
    float* op = out + ((size_t)ql * BATCH + b) * D_MODEL + h * D_K;
#pragma unroll
    for (int d4 = 0; d4 < 16; d4++) {
        float4 v;
        v.x = O[d4 * 4 + 0] * inv;
        v.y = O[d4 * 4 + 1] * inv;
        v.z = O[d4 * 4 + 2] * inv;
        v.w = O[d4 * 4 + 3] * inv;
        *(float4*)(op + d4 * 4) = v;
    }
}

// ---------------------------------------------------------------------------
extern "C" void kernel_launch(void* const* d_in, const int* in_sizes, int n_in,
                              void* d_out, int out_size) {
    const float* x = (const float*)d_in[0];          // [L, B, 1024]
    const float* w = (const float*)d_in[1];          // [3072, 1024]
    float* out = (float*)d_out;                      // [L, B, 1024]

    float *qkv, *Qp, *Kp, *Vp;
    __nv_bfloat16 *xhi, *xlo, *whi, *wlo;
    cudaGetSymbolAddress((void**)&qkv, g_qkv);
    cudaGetSymbolAddress((void**)&Qp, g_Q);
    cudaGetSymbolAddress((void**)&Kp, g_K);
    cudaGetSymbolAddress((void**)&Vp, g_V);
    cudaGetSymbolAddress((void**)&xhi, g_Xhi);
    cudaGetSymbolAddress((void**)&xlo, g_Xlo);
    cudaGetSymbolAddress((void**)&whi, g_Whi);
    cudaGetSymbolAddress((void**)&wlo, g_Wlo);

    // Split X and W into bf16 hi/lo
    int nx4 = M_ROWS * K_DIM / 4;
    int nw4 = N_COLS * K_DIM / 4;
    split_bf16<<<(nx4 + 255) / 256, 256>>>(x, xhi, xlo, nx4);
    split_bf16<<<(nw4 + 255) / 256, 256>>>(w, whi, wlo, nw4);

    // Tensor-core QKV GEMM
    dim3 ggrid(N_COLS / 128, M_ROWS / 128);          // (24, 32)
    qkv_gemm_mma<<<ggrid, 256>>>(xhi, xlo, whi, wlo, qkv);

    int total = L_SEQ * BATCH * NHEAD * D_K;
    rope_scatter<<<(total + 255) / 256, 256>>>(qkv, Qp, Kp, Vp);

    dim3 agrid(L_SEQ / AQ, NHEAD * BATCH);
    flash_attn<<<agrid, 128>>>(Qp, Kp, Vp, out);
}

// round 11
// speedup vs baseline: 2.7185x; 2.3420x over previous
#include <cuda_runtime.h>
#include <cuda_bf16.h>
#include <math.h>
#include <stdint.h>

// Problem constants
#define L_SEQ   2048
#define BATCH   2
#define D_MODEL 1024
#define NHEAD   16
#define D_K     64
#define D_ROPE  32
#define M_ROWS  (L_SEQ * BATCH)        // 4096
#define N_COLS  (3 * D_MODEL)          // 3072
#define K_DIM   D_MODEL                // 1024
#define HB      (NHEAD * BATCH)        // 32

// Scratch (device globals — no runtime allocation allowed)
__device__ float g_qkv[M_ROWS * N_COLS];                 // [r][e]

// Split-bf16 copies of X and W (hi + residual lo)
__device__ __nv_bfloat16 g_Xhi[M_ROWS * K_DIM];
__device__ __nv_bfloat16 g_Xlo[M_ROWS * K_DIM];
__device__ __nv_bfloat16 g_Whi[N_COLS * K_DIM];
__device__ __nv_bfloat16 g_Wlo[N_COLS * K_DIM];

// Split-bf16 attention operands.  Q scaled by 1/8 before split.
// Q,K: [hb][l][d]   Vt: [hb][d][l]  (transposed for PV B-fragments)
__device__ __nv_bfloat16 g_Qhi[HB * L_SEQ * D_K];
__device__ __nv_bfloat16 g_Qlo[HB * L_SEQ * D_K];
__device__ __nv_bfloat16 g_Khi[HB * L_SEQ * D_K];
__device__ __nv_bfloat16 g_Klo[HB * L_SEQ * D_K];
__device__ __nv_bfloat16 g_Vthi[HB * D_K * L_SEQ];
__device__ __nv_bfloat16 g_Vtlo[HB * D_K * L_SEQ];

// ---------------------------------------------------------------------------
// Helpers
// ---------------------------------------------------------------------------
__device__ __forceinline__ uint32_t pack_bf16x2(float lo, float hi) {
    uint32_t r;
    asm("cvt.rn.bf16x2.f32 %0, %1, %2;" : "=r"(r) : "f"(hi), "f"(lo));
    return r;
}
__device__ __forceinline__ float bf16_res(float x) {
    return x - __bfloat162float(__float2bfloat16_rn(x));
}

// mma.sync m16n8k16 bf16 (baseline PTX — works on plain sm_103 target)
__device__ __forceinline__ void mma16816(float* c,
                                         uint32_t a0, uint32_t a1, uint32_t a2, uint32_t a3,
                                         uint32_t b0, uint32_t b1) {
    asm volatile(
        "mma.sync.aligned.m16n8k16.row.col.f32.bf16.bf16.f32 "
        "{%0,%1,%2,%3}, {%4,%5,%6,%7}, {%8,%9}, {%0,%1,%2,%3};"
        : "+f"(c[0]), "+f"(c[1]), "+f"(c[2]), "+f"(c[3])
        : "r"(a0), "r"(a1), "r"(a2), "r"(a3), "r"(b0), "r"(b1));
}

// ---------------------------------------------------------------------------
// Kernel 0: fp32 -> split bf16 (hi = rn(x), lo = rn(x - hi)); 4 floats/thread
// ---------------------------------------------------------------------------
__global__ __launch_bounds__(256) void split_bf16(const float* __restrict__ src,
                                                  __nv_bfloat16* __restrict__ hi,
                                                  __nv_bfloat16* __restrict__ lo,
                                                  int n4) {
    int i = blockIdx.x * blockDim.x + threadIdx.x;
    if (i >= n4) return;
    float4 v = ((const float4*)src)[i];
    float r0 = bf16_res(v.x), r1 = bf16_res(v.y), r2 = bf16_res(v.z), r3 = bf16_res(v.w);
    uint2 hv, lv;
    hv.x = pack_bf16x2(v.x, v.y);
    hv.y = pack_bf16x2(v.z, v.w);
    lv.x = pack_bf16x2(r0, r1);
    lv.y = pack_bf16x2(r2, r3);
    ((uint2*)hi)[i] = hv;
    ((uint2*)lo)[i] = lv;
}

// ---------------------------------------------------------------------------
// Kernel 1: QKV projection C[r][e] = sum_d X[r][d] * W[e][d]
// Tensor-core bf16 split (3 terms), BM=128, BN=128, BK=32. (unchanged, proven)
// ---------------------------------------------------------------------------
#define GBK 32
#define APAD 40

__global__ __launch_bounds__(256) void qkv_gemm_mma(const __nv_bfloat16* __restrict__ Xhi,
                                                    const __nv_bfloat16* __restrict__ Xlo,
                                                    const __nv_bfloat16* __restrict__ Whi,
                                                    const __nv_bfloat16* __restrict__ Wlo,
                                                    float* __restrict__ C) {
    __shared__ __align__(16) __nv_bfloat16 Ahi[128 * APAD];
    __shared__ __align__(16) __nv_bfloat16 Alo[128 * APAD];
    __shared__ __align__(16) __nv_bfloat16 Bhi[128 * APAD];
    __shared__ __align__(16) __nv_bfloat16 Blo[128 * APAD];

    const int tid = threadIdx.x;
    const int lane = tid & 31;
    const int wid = tid >> 5;
    const int warp_m = wid & 1;
    const int warp_n = wid >> 1;
    const int qr = lane >> 2;
    const int qc = lane & 3;

    const int bm = blockIdx.y * 128;
    const int bn = blockIdx.x * 128;

    float acc[4][4][4];
#pragma unroll
    for (int fm = 0; fm < 4; fm++)
#pragma unroll
        for (int fn = 0; fn < 4; fn++)
#pragma unroll
            for (int x = 0; x < 4; x++) acc[fm][fn][x] = 0.f;

    for (int ch = 0; ch < K_DIM / GBK; ch++) {
        const int k0 = ch * GBK;
#pragma unroll
        for (int it = 0; it < 2; it++) {
            const int s = it * 256 + tid;
            const int row = s >> 2;
            const int c8 = s & 3;
            const size_t goff = (size_t)row * K_DIM + k0 + c8 * 8;
            const int soff = row * APAD + c8 * 8;
            *(uint4*)(Ahi + soff) = *(const uint4*)(Xhi + (size_t)bm * K_DIM + goff);
            *(uint4*)(Alo + soff) = *(const uint4*)(Xlo + (size_t)bm * K_DIM + goff);
            *(uint4*)(Bhi + soff) = *(const uint4*)(Whi + (size_t)bn * K_DIM + goff);
            *(uint4*)(Blo + soff) = *(const uint4*)(Wlo + (size_t)bn * K_DIM + goff);
        }
        __syncthreads();

        const __nv_bfloat16* Ap[3] = {Ahi, Ahi, Alo};
        const __nv_bfloat16* Bp[3] = {Bhi, Blo, Bhi};
#pragma unroll
        for (int t = 0; t < 3; t++) {
            const __nv_bfloat16* As = Ap[t];
            const __nv_bfloat16* Bs = Bp[t];
#pragma unroll
            for (int ks = 0; ks < 2; ks++) {
                const int koff = ks * 16 + qc * 2;
                uint32_t a[4][4];
#pragma unroll
                for (int fm = 0; fm < 4; fm++) {
                    const int r0 = warp_m * 64 + fm * 16 + qr;
                    a[fm][0] = *(const uint32_t*)(As + r0 * APAD + koff);
                    a[fm][1] = *(const uint32_t*)(As + (r0 + 8) * APAD + koff);
                    a[fm][2] = *(const uint32_t*)(As + r0 * APAD + koff + 8);
                    a[fm][3] = *(const uint32_t*)(As + (r0 + 8) * APAD + koff + 8);
                }
                uint32_t b[4][2];
#pragma unroll
                for (int fn = 0; fn < 4; fn++) {
                    const int n0 = warp_n * 32 + fn * 8 + qr;
                    b[fn][0] = *(const uint32_t*)(Bs + n0 * APAD + koff);
                    b[fn][1] = *(const uint32_t*)(Bs + n0 * APAD + koff + 8);
                }
#pragma unroll
                for (int fm = 0; fm < 4; fm++)
#pragma unroll
                    for (int fn = 0; fn < 4; fn++)
                        mma16816(acc[fm][fn], a[fm][0], a[fm][1], a[fm][2], a[fm][3],
                                 b[fn][0], b[fn][1]);
            }
        }
        __syncthreads();
    }

#pragma unroll
    for (int fm = 0; fm < 4; fm++) {
        const int r0 = bm + warp_m * 64 + fm * 16 + qr;
#pragma unroll
        for (int fn = 0; fn < 4; fn++) {
            const int col = bn + warp_n * 32 + fn * 8 + qc * 2;
            float2 v0 = {acc[fm][fn][0], acc[fm][fn][1]};
            float2 v1 = {acc[fm][fn][2], acc[fm][fn][3]};
            *(float2*)(C + (size_t)r0 * N_COLS + col) = v0;
            *(float2*)(C + (size_t)(r0 + 8) * N_COLS + col) = v1;
        }
    }
}

// ---------------------------------------------------------------------------
// Kernel 2: RoPE + scatter qkv -> split-bf16 Q (scaled), K, and transposed V
// ---------------------------------------------------------------------------
__global__ __launch_bounds__(256) void rope_scatter(const float* __restrict__ qkv,
                                                    __nv_bfloat16* __restrict__ Qh,
                                                    __nv_bfloat16* __restrict__ Ql,
                                                    __nv_bfloat16* __restrict__ Kh,
                                                    __nv_bfloat16* __restrict__ Kl,
                                                    __nv_bfloat16* __restrict__ Vh,
                                                    __nv_bfloat16* __restrict__ Vl) {
    int idx = blockIdx.x * blockDim.x + threadIdx.x;
    if (idx >= L_SEQ * BATCH * NHEAD * D_K) return;
    const int d = idx & 63;
    const int h = (idx >> 6) & 15;
    const int r = idx >> 10;
    const int l = r >> 1;
    const int b = r & 1;

    const float* row = qkv + (size_t)r * N_COLS + h * (3 * D_K);
    float q = row[d];
    float k = row[D_K + d];
    float v = row[2 * D_K + d];

    if (d < D_ROPE) {
        const int i = d & 15;
        float theta = (float)exp2(-(double)i * (13.287712379549449 / 16.0));
        float ang = (float)l * theta;
        float cs = cosf(ang);
        float sn = sinf(ang);
        if (d < 16) {
            q = q * cs - row[d + 16] * sn;
            k = k * cs - row[D_K + d + 16] * sn;
        } else {
            q = q * cs + row[d - 16] * sn;
            k = k * cs + row[D_K + d - 16] * sn;
        }
    }
    q *= 0.125f;   // fold softmax scale into Q before split
    const int hb = h * BATCH + b;
    size_t o = ((size_t)hb * L_SEQ + l) * D_K + d;
    size_t ov = ((size_t)hb * D_K + d) * L_SEQ + l;   // transposed V
    Qh[o] = __float2bfloat16_rn(q);
    Ql[o] = __float2bfloat16_rn(bf16_res(q));
    Kh[o] = __float2bfloat16_rn(k);
    Kl[o] = __float2bfloat16_rn(bf16_res(k));
    Vh[ov] = __float2bfloat16_rn(v);
    Vl[ov] = __float2bfloat16_rn(bf16_res(v));
}

// ---------------------------------------------------------------------------
// Kernel 3: Flash attention on tensor cores, split-bf16 (3 terms both GEMMs).
// CTA: 128 queries (8 warps x 16 rows), K/V tiled by 64.  Grid (16, 32).
// ---------------------------------------------------------------------------
#define FSTR 72   // smem row stride in bf16 (64 + 8 pad, conflict-free quad LDS)

__global__ __launch_bounds__(256, 1) void flash_attn_mma(const __nv_bfloat16* __restrict__ Qh,
                                                         const __nv_bfloat16* __restrict__ Ql,
                                                         const __nv_bfloat16* __restrict__ Kh,
                                                         const __nv_bfloat16* __restrict__ Kl,
                                                         const __nv_bfloat16* __restrict__ Vh,
                                                         const __nv_bfloat16* __restrict__ Vl,
                                                         float* __restrict__ out) {
    // 18432 bf16 = 36864 B; phase 1: Q staging (2 x 128 x 72); phase 2: 4 tiles 64 x 72
    __shared__ __align__(16) __nv_bfloat16 smem[4 * 64 * FSTR];

    const int tid = threadIdx.x;
    const int lane = tid & 31;
    const int wid = tid >> 5;         // 0..7
    const int qr = lane >> 2;         // 0..7
    const int qc = lane & 3;          // 0..3

    const int hb = blockIdx.y;
    const int q0 = blockIdx.x * 128;

    // ---- Stage Q tile (128 x 64, hi+lo) into smem, then into A-fragments
    {
        const __nv_bfloat16* Qgh = Qh + ((size_t)hb * L_SEQ + q0) * D_K;
        const __nv_bfloat16* Qgl = Ql + ((size_t)hb * L_SEQ + q0) * D_K;
#pragma unroll
        for (int it = 0; it < 4; it++) {
            const int s = it * 256 + tid;      // 0..1023
            const int row = s >> 3, c8 = s & 7;
            const size_t g = (size_t)row * D_K + c8 * 8;
            *(uint4*)(smem + row * FSTR + c8 * 8) = *(const uint4*)(Qgh + g);
            *(uint4*)(smem + 128 * FSTR + row * FSTR + c8 * 8) = *(const uint4*)(Qgl + g);
        }
    }
    __syncthreads();

    uint32_t qa_h[4][4], qa_l[4][4];
    {
        const int r0 = wid * 16 + qr;
#pragma unroll
        for (int ks = 0; ks < 4; ks++) {
            const int koff = ks * 16 + qc * 2;
            qa_h[ks][0] = *(const uint32_t*)(smem + r0 * FSTR + koff);
            qa_h[ks][1] = *(const uint32_t*)(smem + (r0 + 8) * FSTR + koff);
            qa_h[ks][2] = *(const uint32_t*)(smem + r0 * FSTR + koff + 8);
            qa_h[ks][3] = *(const uint32_t*)(smem + (r0 + 8) * FSTR + koff + 8);
            qa_l[ks][0] = *(const uint32_t*)(smem + (128 + r0) * FSTR + koff);
            qa_l[ks][1] = *(const uint32_t*)(smem + (128 + r0 + 8) * FSTR + koff);
            qa_l[ks][2] = *(const uint32_t*)(smem + (128 + r0) * FSTR + koff + 8);
            qa_l[ks][3] = *(const uint32_t*)(smem + (128 + r0 + 8) * FSTR + koff + 8);
        }
    }
    __syncthreads();

    __nv_bfloat16* sKh = smem;
    __nv_bfloat16* sKl = smem + 64 * FSTR;
    __nv_bfloat16* sVh = smem + 2 * 64 * FSTR;
    __nv_bfloat16* sVl = smem + 3 * 64 * FSTR;

    const __nv_bfloat16* Kgh = Kh + (size_t)hb * L_SEQ * D_K;
    const __nv_bfloat16* Kgl = Kl + (size_t)hb * L_SEQ * D_K;
    const __nv_bfloat16* Vgh = Vh + (size_t)hb * D_K * L_SEQ;
    const __nv_bfloat16* Vgl = Vl + (size_t)hb * D_K * L_SEQ;

    float o[8][4];
#pragma unroll
    for (int fn = 0; fn < 8; fn++)
#pragma unroll
        for (int x = 0; x < 4; x++) o[fn][x] = 0.f;
    float m0 = -1e30f, m1 = -1e30f, l0 = 0.f, l1 = 0.f;

    for (int t = 0; t < L_SEQ / 64; t++) {
        // ---- Load K (rows=key, cols=d) and Vt (rows=d, cols=key) tiles
#pragma unroll
        for (int it = 0; it < 2; it++) {
            const int s = it * 256 + tid;      // 0..511
            const int row = s >> 3, c8 = s & 7;
            const size_t gk = (size_t)(t * 64 + row) * D_K + c8 * 8;
            const size_t gv = (size_t)row * L_SEQ + t * 64 + c8 * 8;
            const int so = row * FSTR + c8 * 8;
            *(uint4*)(sKh + so) = *(const uint4*)(Kgh + gk);
            *(uint4*)(sKl + so) = *(const uint4*)(Kgl + gk);
            *(uint4*)(sVh + so) = *(const uint4*)(Vgh + gv);
            *(uint4*)(sVl + so) = *(const uint4*)(Vgl + gv);
        }
        __syncthreads();

        // ---- S = Q K^T  (3-term split)
        float s[8][4];
#pragma unroll
        for (int fn = 0; fn < 8; fn++)
#pragma unroll
            for (int x = 0; x < 4; x++) s[fn][x] = 0.f;

#pragma unroll
        for (int ks = 0; ks < 4; ks++) {
            const int koff = ks * 16 + qc * 2;
#pragma unroll
            for (int fn = 0; fn < 8; fn++) {
                const int n0 = fn * 8 + qr;
                uint32_t bh0 = *(const uint32_t*)(sKh + n0 * FSTR + koff);
                uint32_t bh1 = *(const uint32_t*)(sKh + n0 * FSTR + koff + 8);
                uint32_t bl0 = *(const uint32_t*)(sKl + n0 * FSTR + koff);
                uint32_t bl1 = *(const uint32_t*)(sKl + n0 * FSTR + koff + 8);
                mma16816(s[fn], qa_h[ks][0], qa_h[ks][1], qa_h[ks][2], qa_h[ks][3], bh0, bh1);
                mma16816(s[fn], qa_h[ks][0], qa_h[ks][1], qa_h[ks][2], qa_h[ks][3], bl0, bl1);
                mma16816(s[fn], qa_l[ks][0], qa_l[ks][1], qa_l[ks][2], qa_l[ks][3], bh0, bh1);
            }
        }

        // ---- Online softmax (rows qr -> c0,c1 ; qr+8 -> c2,c3)
        float mx0 = m0, mx1 = m1;
#pragma unroll
        for (int fn = 0; fn < 8; fn++) {
            mx0 = fmaxf(mx0, fmaxf(s[fn][0], s[fn][1]));
            mx1 = fmaxf(mx1, fmaxf(s[fn][2], s[fn][3]));
        }
        mx0 = fmaxf(mx0, __shfl_xor_sync(0xffffffffu, mx0, 1));
        mx0 = fmaxf(mx0, __shfl_xor_sync(0xffffffffu, mx0, 2));
        mx1 = fmaxf(mx1, __shfl_xor_sync(0xffffffffu, mx1, 1));
        mx1 = fmaxf(mx1, __shfl_xor_sync(0xffffffffu, mx1, 2));

        const float c0 = __expf(m0 - mx0);
        const float c1 = __expf(m1 - mx1);
        m0 = mx0; m1 = mx1;

        float ps0 = 0.f, ps1 = 0.f;
#pragma unroll
        for (int fn = 0; fn < 8; fn++) {
            s[fn][0] = __expf(s[fn][0] - mx0); ps0 += s[fn][0];
            s[fn][1] = __expf(s[fn][1] - mx0); ps0 += s[fn][1];
            s[fn][2] = __expf(s[fn][2] - mx1); ps1 += s[fn][2];
            s[fn][3] = __expf(s[fn][3] - mx1); ps1 += s[fn][3];
        }
        ps0 += __shfl_xor_sync(0xffffffffu, ps0, 1);
        ps0 += __shfl_xor_sync(0xffffffffu, ps0, 2);
        ps1 += __shfl_xor_sync(0xffffffffu, ps1, 1);
        ps1 += __shfl_xor_sync(0xffffffffu, ps1, 2);
        l0 = l0 * c0 + ps0;
        l1 = l1 * c1 + ps1;

#pragma unroll
        for (int fn = 0; fn < 8; fn++) {
            o[fn][0] *= c0; o[fn][1] *= c0;
            o[fn][2] *= c1; o[fn][3] *= c1;
        }

        // ---- Pack P into A-fragments: C(m16n8 x2) layout == A(m16k16) layout
        uint32_t pa_h[4][4], pa_l[4][4];
#pragma unroll
        for (int k2 = 0; k2 < 4; k2++) {
            const float* e = s[2 * k2];
            const float* f = s[2 * k2 + 1];
            pa_h[k2][0] = pack_bf16x2(e[0], e[1]);
            pa_h[k2][1] = pack_bf16x2(e[2], e[3]);
            pa_h[k2][2] = pack_bf16x2(f[0], f[1]);
            pa_h[k2][3] = pack_bf16x2(f[2], f[3]);
            pa_l[k2][0] = pack_bf16x2(bf16_res(e[0]), bf16_res(e[1]));
            pa_l[k2][1] = pack_bf16x2(bf16_res(e[2]), bf16_res(e[3]));
            pa_l[k2][2] = pack_bf16x2(bf16_res(f[0]), bf16_res(f[1]));
            pa_l[k2][3] = pack_bf16x2(bf16_res(f[2]), bf16_res(f[3]));
        }

        // ---- O += P V  (3-term split; B from transposed V)
#pragma unroll
        for (int k2 = 0; k2 < 4; k2++) {
            const int koff = k2 * 16 + qc * 2;
#pragma unroll
            for (int fn = 0; fn < 8; fn++) {
                const int d0 = fn * 8 + qr;
                uint32_t bh0 = *(const uint32_t*)(sVh + d0 * FSTR + koff);
                uint32_t bh1 = *(const uint32_t*)(sVh + d0 * FSTR + koff + 8);
                uint32_t bl0 = *(const uint32_t*)(sVl + d0 * FSTR + koff);
                uint32_t bl1 = *(const uint32_t*)(sVl + d0 * FSTR + koff + 8);
                mma16816(o[fn], pa_h[k2][0], pa_h[k2][1], pa_h[k2][2], pa_h[k2][3], bh0, bh1);
                mma16816(o[fn], pa_h[k2][0], pa_h[k2][1], pa_h[k2][2], pa_h[k2][3], bl0, bl1);
                mma16816(o[fn], pa_l[k2][0], pa_l[k2][1], pa_l[k2][2], pa_l[k2][3], bh0, bh1);
            }
        }
        __syncthreads();
    }

    // ---- Epilogue: normalize, store to out [l][b][h*64+d]
    const float inv0 = 1.f / l0;
    const float inv1 = 1.f / l1;
    const int h = hb >> 1, b = hb & 1;
    const int row0 = q0 + wid * 16 + qr;
#pragma unroll
    for (int fn = 0; fn < 8; fn++) {
        const int col = h * D_K + fn * 8 + qc * 2;
        float2 v0 = {o[fn][0] * inv0, o[fn][1] * inv0};
        float2 v1 = {o[fn][2] * inv1, o[fn][3] * inv1};
        *(float2*)(out + ((size_t)row0 * BATCH + b) * D_MODEL + col) = v0;
        *(float2*)(out + ((size_t)(row0 + 8) * BATCH + b) * D_MODEL + col) = v1;
    }
}

// ---------------------------------------------------------------------------
extern "C" void kernel_launch(void* const* d_in, const int* in_sizes, int n_in,
                              void* d_out, int out_size) {
    const float* x = (const float*)d_in[0];          // [L, B, 1024]
    const float* w = (const float*)d_in[1];          // [3072, 1024]
    float* out = (float*)d_out;                      // [L, B, 1024]

    float* qkv;
    __nv_bfloat16 *xhi, *xlo, *whi, *wlo;
    __nv_bfloat16 *qh, *ql, *kh, *kl, *vh, *vl;
    cudaGetSymbolAddress((void**)&qkv, g_qkv);
    cudaGetSymbolAddress((void**)&xhi, g_Xhi);
    cudaGetSymbolAddress((void**)&xlo, g_Xlo);
    cudaGetSymbolAddress((void**)&whi, g_Whi);
    cudaGetSymbolAddress((void**)&wlo, g_Wlo);
    cudaGetSymbolAddress((void**)&qh, g_Qhi);
    cudaGetSymbolAddress((void**)&ql, g_Qlo);
    cudaGetSymbolAddress((void**)&kh, g_Khi);
    cudaGetSymbolAddress((void**)&kl, g_Klo);
    cudaGetSymbolAddress((void**)&vh, g_Vthi);
    cudaGetSymbolAddress((void**)&vl, g_Vtlo);

    // Split X and W into bf16 hi/lo
    int nx4 = M_ROWS * K_DIM / 4;
    int nw4 = N_COLS * K_DIM / 4;
    split_bf16<<<(nx4 + 255) / 256, 256>>>(x, xhi, xlo, nx4);
    split_bf16<<<(nw4 + 255) / 256, 256>>>(w, whi, wlo, nw4);

    // Tensor-core QKV GEMM
    dim3 ggrid(N_COLS / 128, M_ROWS / 128);          // (24, 32)
    qkv_gemm_mma<<<ggrid, 256>>>(xhi, xlo, whi, wlo, qkv);

    // RoPE + split/scatter
    int total = L_SEQ * BATCH * NHEAD * D_K;
    rope_scatter<<<(total + 255) / 256, 256>>>(qkv, qh, ql, kh, kl, vh, vl);

    // Tensor-core flash attention
    dim3 agrid(L_SEQ / 128, HB);                     // (16, 32)
    flash_attn_mma<<<agrid, 256>>>(qh, ql, kh, kl, vh, vl, out);
}